// round 15
// baseline (speedup 1.0000x reference)
#include <cuda_runtime.h>

#define B_ 16
#define C_ 512
#define N_ 4096
#define K_ 32

// 8 MB scratch for softmax weights w[b][n][k]
__device__ __align__(16) float g_w[B_ * N_ * K_];

typedef unsigned long long ull;

__device__ __forceinline__ ull pk2(float a, float b) {
    ull r; asm("mov.b64 %0, {%1, %2};" : "=l"(r) : "f"(a), "f"(b)); return r;
}
__device__ __forceinline__ void ffma2(ull &d, ull a, ull b) {
    asm("fma.rn.f32x2 %0, %1, %2, %0;" : "+l"(d) : "l"(a), "l"(b));
}
__device__ __forceinline__ void upk2(ull v, float &a, float &b) {
    asm("mov.b64 {%0, %1}, %2;" : "=f"(a), "=f"(b) : "l"(v));
}
__device__ __forceinline__ ull lds_u64(unsigned a) {
    ull v; asm volatile("ld.shared.b64 %0, [%1];" : "=l"(v) : "r"(a)); return v;
}
__device__ __forceinline__ void lds_v2_u64(unsigned addr, ull &a, ull &b) {
    asm volatile("ld.shared.v2.b64 {%0, %1}, [%2];" : "=l"(a), "=l"(b) : "r"(addr));
}
__device__ __forceinline__ float4 lds128(unsigned a) {
    float4 v;
    asm volatile("ld.shared.v4.f32 {%0,%1,%2,%3}, [%4];"
                 : "=f"(v.x), "=f"(v.y), "=f"(v.z), "=f"(v.w) : "r"(a));
    return v;
}

// ================= kernel 1: assign (xc gemm + softmax -> g_w, zeroes out) ==============
// Persistent: grid 256 blocks x 256 threads (2 blocks/SM -> single wave), 2 token-tiles
// of 128 tokens per block. Inner code = best-measured R7 version, unchanged.
#define XSA 0
#define CWSA 4224
#define SQO 5376
#define SAO 6400
#define SDO 6432
#define ASM_WORDS 6464

__global__ void __launch_bounds__(256, 2) assign_kernel(const float *__restrict__ x,
                                                        const float *__restrict__ cw,
                                                        const float *__restrict__ scale,
                                                        float *__restrict__ out) {
    __shared__ __align__(16) float sm[ASM_WORDS];
    const int t = threadIdx.x;

    // fold output zeroing: 256 blocks * 256 threads * float4 = 262144 floats = B*K*C
    reinterpret_cast<float4 *>(out)[blockIdx.x * 256 + t] = make_float4(0.f, 0.f, 0.f, 0.f);

    const int L = t & 31, wmid = t >> 5, kg = wmid & 3, th = wmid >> 2;
    const int q = t & 31, kA = t >> 3, c4 = (t & 7) * 4;
    const unsigned smb = (unsigned)__cvta_generic_to_shared(sm);

#pragma unroll 1
    for (int it = 0; it < 2; ++it) {
        const int T0 = (blockIdx.x + 256 * it) * 128;       // global token base
        const float *xb = x + (size_t)(T0 >> 12) * C_ * N_ + (T0 & (N_ - 1));

        ull acc[8];
#pragma unroll
        for (int m = 0; m < 8; ++m) acc[m] = 0ull;
        float4 xsq4 = make_float4(0.f, 0.f, 0.f, 0.f);
        float csq = 0.f;

#pragma unroll 1
        for (int cc = 0; cc < C_; cc += 32) {
            __syncthreads();
            // stage x chunk [32 c][128 n]: 4 float4/thread -> xsq partials
#pragma unroll
            for (int j = 0; j < 4; ++j) {
                const int c = (t >> 5) + 8 * j;
                float4 v = *reinterpret_cast<const float4 *>(xb + (size_t)(cc + c) * N_ + 4 * q);
                *reinterpret_cast<float4 *>(&sm[XSA + c * 128 + 4 * q]) = v;
                xsq4.x = fmaf(v.x, v.x, xsq4.x); xsq4.y = fmaf(v.y, v.y, xsq4.y);
                xsq4.z = fmaf(v.z, v.z, xsq4.z); xsq4.w = fmaf(v.w, v.w, xsq4.w);
            }
            // stage cw chunk transposed [32 c][32 k] pitch 36 (+ csq partial)
            {
                float4 a = *reinterpret_cast<const float4 *>(cw + (size_t)kA * C_ + cc + c4);
                sm[CWSA + (c4 + 0) * 36 + kA] = a.x;
                sm[CWSA + (c4 + 1) * 36 + kA] = a.y;
                sm[CWSA + (c4 + 2) * 36 + kA] = a.z;
                sm[CWSA + (c4 + 3) * 36 + kA] = a.w;
                csq = fmaf(a.x, a.x, csq); csq = fmaf(a.y, a.y, csq);
                csq = fmaf(a.z, a.z, csq); csq = fmaf(a.w, a.w, csq);
            }
            __syncthreads();

#pragma unroll 4
            for (int c = 0; c < 32; ++c) {
                ull xp = lds_u64(smb + (unsigned)((XSA + c * 128 + 64 * th + 2 * L) * 4));
                float4 w0 = lds128(smb + (unsigned)((CWSA + c * 36 + 8 * kg) * 4));
                float4 w1 = lds128(smb + (unsigned)((CWSA + c * 36 + 8 * kg + 4) * 4));
                ffma2(acc[0], xp, pk2(w0.x, w0.x)); ffma2(acc[1], xp, pk2(w0.y, w0.y));
                ffma2(acc[2], xp, pk2(w0.z, w0.z)); ffma2(acc[3], xp, pk2(w0.w, w0.w));
                ffma2(acc[4], xp, pk2(w1.x, w1.x)); ffma2(acc[5], xp, pk2(w1.y, w1.y));
                ffma2(acc[6], xp, pk2(w1.z, w1.z)); ffma2(acc[7], xp, pk2(w1.w, w1.w));
            }
        }
        __syncthreads();   // mainloop xs reads done before sxc overwrite

        // exchange xc -> sxc[tok][k] pitch 33
        {
            const int tok = 64 * th + 2 * L;
#pragma unroll
            for (int kk = 0; kk < 8; ++kk) {
                float lo, hi;
                upk2(acc[kk], lo, hi);
                sm[XSA + tok * 33 + 8 * kg + kk] = lo;
                sm[XSA + (tok + 1) * 33 + 8 * kg + kk] = hi;
            }
        }
        *reinterpret_cast<float4 *>(&sm[SQO + (t >> 5) * 128 + 4 * q]) = xsq4;
#pragma unroll
        for (int d = 1; d < 8; d <<= 1) csq += __shfl_xor_sync(0xffffffffu, csq, d);
        if ((t & 7) == 0) {
            float s = scale[kA];
            sm[SAO + kA] = s;
            sm[SDO + kA] = s * csq;
        }
        __syncthreads();

        // softmax: thread t<128 handles token t
        if (t < 128) {
            float xsq = 0.f;
#pragma unroll
            for (int r = 0; r < 8; ++r) xsq += sm[SQO + r * 128 + t];
            float l[K_];
            float mx = -1e30f;
#pragma unroll
            for (int k = 0; k < K_; ++k) {
                float lv = sm[SAO + k] * (xsq - 2.0f * sm[XSA + t * 33 + k]) + sm[SDO + k];
                l[k] = lv; mx = fmaxf(mx, lv);
            }
            float s = 0.f;
#pragma unroll
            for (int k = 0; k < K_; ++k) { float e = __expf(l[k] - mx); l[k] = e; s += e; }
            float inv = 1.0f / s;
#pragma unroll
            for (int k = 0; k < K_; ++k) sm[XSA + t * 33 + k] = l[k] * inv;
        }
        __syncthreads();

        // coalesced copy sxc -> g_w (4096 floats)
        float *gw = g_w + (size_t)T0 * K_;
#pragma unroll
        for (int i = 0; i < 16; ++i) {
            const int f = t + 256 * i;
            gw[f] = sm[XSA + (f >> 5) * 33 + (f & 31)];
        }
        __syncthreads();   // iteration boundary: gw reads of sm done before next tile's STS
    }
}

// ================= kernel 2: aggregate (best-measured 66.4us version, persistent) ========
// Persistent: grid 512 blocks x 128 threads (4 blocks/SM -> single wave), 2 tiles/block.
// Tile = (128 n) x (256 c half) x (all 32 k); thread owns c-pair x 32 k (32 packed acc).
#define AGG_NC 128
#define AGG_NS 16
#define XP 258

__global__ void __launch_bounds__(128, 4) aggregate_kernel(const float *__restrict__ x,
                                                           const float *__restrict__ cw,
                                                           float *__restrict__ out) {
    __shared__ __align__(16) float ws[AGG_NC * K_];          // 16 KB: w rows [i][32k]
    __shared__ __align__(16) float xs[AGG_NS * XP];          // ~16.5 KB: x subtile [n][256c]
    __shared__ float part[128];
    __shared__ float wsf[K_];

    const int t = threadIdx.x;
    const int c0l = 2 * t;            // local c (0..255) pair owned by this thread
    const unsigned wsb = (unsigned)__cvta_generic_to_shared(ws);
    const unsigned xsb = (unsigned)__cvta_generic_to_shared(xs);

#pragma unroll 1
    for (int it = 0; it < 2; ++it) {
        const int tile = blockIdx.x + 512 * it;              // 1024 tiles total
        const int n0 = (tile & 31) * AGG_NC;
        const int b = (tile >> 5) & 15;
        const int cbase = (tile >> 9) * 256;

        __syncthreads();   // previous tile fully done before ws overwrite
        // load w chunk [128 n][32 k] (coalesced float4)
        {
            const float4 *gw4 = reinterpret_cast<const float4 *>(g_w + ((size_t)b * N_ + n0) * K_);
            float4 *ws4 = reinterpret_cast<float4 *>(ws);
#pragma unroll
            for (int j = 0; j < 8; ++j) ws4[t + 128 * j] = gw4[t + 128 * j];
        }

        ull acc[32];
#pragma unroll
        for (int m = 0; m < 32; ++m) acc[m] = 0ull;

        const float *xg = x + ((size_t)b * C_ + cbase) * N_ + n0;

#pragma unroll 1
        for (int s = 0; s < AGG_NC / AGG_NS; ++s) {
            __syncthreads();   // xs free to overwrite (also orders ws load on s==0)
            // stage subtile: 256 c x 16 n -> xs[n][c], 8 float4 per thread
#pragma unroll
            for (int j = 0; j < 8; ++j) {
                int flat = t + 128 * j;          // 0..1023
                int c = flat >> 2;               // local c 0..255
                int qq = flat & 3;               // n-quad within subtile
                float4 v = *reinterpret_cast<const float4 *>(xg + (size_t)c * N_ + s * AGG_NS + 4 * qq);
                xs[(4 * qq + 0) * XP + c] = v.x;
                xs[(4 * qq + 1) * XP + c] = v.y;
                xs[(4 * qq + 2) * XP + c] = v.z;
                xs[(4 * qq + 3) * XP + c] = v.w;
            }
            __syncthreads();

#pragma unroll 2
            for (int nn = 0; nn < AGG_NS; ++nn) {
                const int i = s * AGG_NS + nn;
                ull xpair = lds_u64(xsb + (unsigned)((nn * XP + c0l) * 4));
                float x0, x1;
                upk2(xpair, x0, x1);
                ull xx0 = pk2(x0, x0);
                ull xx1 = pk2(x1, x1);
                unsigned rowa = wsb + (unsigned)i * (K_ * 4);
#pragma unroll
                for (int j = 0; j < 8; ++j) {      // broadcast w reads (raw packed pairs)
                    ull w0, w1;
                    lds_v2_u64(rowa + j * 16u, w0, w1);
                    ffma2(acc[2 * j], xx0, w0);
                    ffma2(acc[2 * j + 1], xx0, w1);
                    ffma2(acc[16 + 2 * j], xx1, w0);
                    ffma2(acc[16 + 2 * j + 1], xx1, w1);
                }
            }
        }

        // per-block wsum over this n-chunk (conflict-free: bank = k)
        {
            float lws = 0.0f;
            const int kk = t & 31;
            const int r = t >> 5;   // 0..3
#pragma unroll
            for (int j = 0; j < 32; ++j) lws += ws[(r + 4 * j) * K_ + kk];
            part[t] = lws;
        }
        __syncthreads();
        if (t < K_) {
            float s = 0.f;
#pragma unroll
            for (int qq = 0; qq < 4; ++qq) s += part[t + 32 * qq];
            wsf[t] = s;
        }
        __syncthreads();

        // epilogue: fold -wsum*cw locally, reduce to global (coalesced red.global.f32)
        const int cg = cbase + c0l;
        float *ob = out + (size_t)b * K_ * C_;
#pragma unroll
        for (int m = 0; m < 16; ++m) {
            const int k = 2 * m;
            float a0, a1, b0, b1;
            upk2(acc[m], a0, a1);          // a0:(k,cg)   a1:(k+1,cg)
            upk2(acc[16 + m], b0, b1);     // b0:(k,cg+1) b1:(k+1,cg+1)
            float wk0 = wsf[k];
            float wk1 = wsf[k + 1];
            float2 cw0 = *reinterpret_cast<const float2 *>(&cw[(size_t)k * C_ + cg]);
            float2 cw1 = *reinterpret_cast<const float2 *>(&cw[(size_t)(k + 1) * C_ + cg]);
            atomicAdd(&ob[(size_t)k * C_ + cg], a0 - wk0 * cw0.x);
            atomicAdd(&ob[(size_t)k * C_ + cg + 1], b0 - wk0 * cw0.y);
            atomicAdd(&ob[(size_t)(k + 1) * C_ + cg], a1 - wk1 * cw1.x);
            atomicAdd(&ob[(size_t)(k + 1) * C_ + cg + 1], b1 - wk1 * cw1.y);
        }
    }
}

extern "C" void kernel_launch(void *const *d_in, const int *in_sizes, int n_in,
                              void *d_out, int out_size) {
    const float *x = (const float *)d_in[0];
    const float *cwp = (const float *)d_in[1];
    const float *scale = (const float *)d_in[2];
    float *out = (float *)d_out;

    assign_kernel<<<256, 256>>>(x, cwp, scale, out);
    aggregate_kernel<<<512, 128>>>(x, cwp, out);
}